// round 3
// baseline (speedup 1.0000x reference)
#include <cuda_runtime.h>
#include <math.h>

#define BN_INV 0.9999950000374997f

typedef unsigned long long u64;

__device__ __forceinline__ u64 ffma2(u64 a, u64 b, u64 c) {
    u64 d;
    asm("fma.rn.f32x2 %0, %1, %2, %3;" : "=l"(d) : "l"(a), "l"(b), "l"(c));
    return d;
}
__device__ __forceinline__ u64 pack2(float lo, float hi) {
    u64 r;
    asm("mov.b64 %0, {%1, %2};" : "=l"(r) : "f"(lo), "f"(hi));
    return r;
}
__device__ __forceinline__ float2 unpack2(u64 v) {
    float2 f;
    asm("mov.b64 {%0, %1}, %2;" : "=f"(f.x), "=f"(f.y) : "l"(v));
    return f;
}

// Scratch (allocation-free rule -> __device__ globals)
__device__ float2 g_h1p[1024 * 4608];   // stage1 out, pair-interleaved [B/2][32*12*12]{s0,s1}
__device__ float2 g_h2p[1024 * 1024];   // stage2 out, pair-interleaved [B/2][1024]{s0,s1}
__device__ float  g_w1t[1024 * 512];    // fc1 weights transposed [k][oc]

// ---------------------------------------------------------------------------
// Paired block reduce (256 threads = 8 warps); sred must hold >= 16 floats
// ---------------------------------------------------------------------------
__device__ __forceinline__ float2 blockReduceSum2(float2 v, volatile float* sred, int tid) {
#pragma unroll
    for (int o = 16; o > 0; o >>= 1) {
        v.x += __shfl_xor_sync(0xffffffffu, v.x, o);
        v.y += __shfl_xor_sync(0xffffffffu, v.y, o);
    }
    if ((tid & 31) == 0) {
        sred[(tid >> 5) * 2]     = v.x;
        sred[(tid >> 5) * 2 + 1] = v.y;
    }
    __syncthreads();
    if (tid < 32) {
        float a = (tid < 8) ? sred[tid * 2] : 0.f;
        float b = (tid < 8) ? sred[tid * 2 + 1] : 0.f;
#pragma unroll
        for (int o = 4; o > 0; o >>= 1) {
            a += __shfl_xor_sync(0xffffffffu, a, o);
            b += __shfl_xor_sync(0xffffffffu, b, o);
        }
        if (tid == 0) { sred[0] = a; sred[1] = b; }
    }
    __syncthreads();
    float2 r = make_float2(sred[0], sred[1]);
    __syncthreads();
    return r;
}

// ---------------------------------------------------------------------------
// Kernel 0: transpose fc1 weights  w1[512][1024] -> g_w1t[1024][512]
// ---------------------------------------------------------------------------
__global__ __launch_bounds__(256) void k_tw1(const float* __restrict__ w1) {
    __shared__ float t[32][33];
    int kb = blockIdx.x * 32;
    int ob = blockIdx.y * 32;
    int lx = threadIdx.x & 31, ly = threadIdx.x >> 5;
#pragma unroll
    for (int r = ly; r < 32; r += 8) t[r][lx] = w1[(ob + r) * 1024 + kb + lx];
    __syncthreads();
#pragma unroll
    for (int r = ly; r < 32; r += 8) g_w1t[(kb + r) * 512 + ob + lx] = t[lx][r];
}

// ---------------------------------------------------------------------------
// Kernel 1: conv1(1->32, 5x5, 28->24) + tern + BN + maxpool2 + relu
// 2 SAMPLES per CTA packed in f32x2 lanes. 256 threads, 3 (oc,oy) tasks each.
// Writes pair-interleaved g_h1p.
// ---------------------------------------------------------------------------
__global__ __launch_bounds__(256) void k_conv1(
    const float* __restrict__ x, const float* __restrict__ w,
    const float* __restrict__ bconv, const float* __restrict__ bng,
    const float* __restrict__ bnb) {
    extern __shared__ float sm[];
    float2* s_in2   = (float2*)sm;            // 28*29 = 812 float2
    float*  s_w     = sm + 1624;              // 800
    float*  s_b     = sm + 2424;              // 32
    float2* s_conv2 = (float2*)(sm + 2456);   // 18432 float2
    __shared__ float sred[16];

    const int n2 = blockIdx.x;
    const int tid = threadIdx.x;

    const float* x0 = x + (2 * n2) * 784;
    const float* x1 = x + (2 * n2 + 1) * 784;
    for (int i = tid; i < 784; i += 256) {
        int r = i / 28, c = i - r * 28;
        s_in2[r * 29 + c] = make_float2(x0[i], x1[i]);
    }
    for (int i = tid; i < 800; i += 256) s_w[i] = w[i];
    if (tid < 32) s_b[tid] = bconv[tid];
    __syncthreads();

    float2 labs = make_float2(0.f, 0.f);
#pragma unroll
    for (int p = 0; p < 3; p++) {
        int pair = tid + p * 256;          // 0..767 = 32 oc * 24 oy
        int oc = pair / 24, oy = pair - oc * 24;
        u64 acc[24];
        {
            float b = s_b[oc];
            u64 bb = pack2(b, b);
#pragma unroll
            for (int ox = 0; ox < 24; ox++) acc[ox] = bb;
        }
#pragma unroll
        for (int kh = 0; kh < 5; kh++) {
            u64 row[28];
            const u64* rp = (const u64*)(s_in2 + (oy + kh) * 29);
#pragma unroll
            for (int j = 0; j < 28; j++) row[j] = rp[j];
            const float* wp = s_w + oc * 25 + kh * 5;
#pragma unroll
            for (int kw = 0; kw < 5; kw++) {
                float s = wp[kw];
                u64 wd = pack2(s, s);
#pragma unroll
                for (int ox = 0; ox < 24; ox++)
                    acc[ox] = ffma2(wd, row[ox + kw], acc[ox]);
            }
        }
        float2* cp = s_conv2 + oc * 576 + oy * 24;
#pragma unroll
        for (int ox = 0; ox < 24; ox++) {
            float2 v = unpack2(acc[ox]);
            cp[ox] = v;
            labs.x += fabsf(v.x);
            labs.y += fabsf(v.y);
        }
    }

    float2 tot = blockReduceSum2(labs, sred, tid);
    float d0 = 0.7f * tot.x / 18432.0f;
    float d1 = 0.7f * tot.y / 18432.0f;

    float2 ms = make_float2(0.f, 0.f), cn = make_float2(0.f, 0.f);
    for (int i = tid; i < 18432; i += 256) {
        float2 v = s_conv2[i];
        float a;
        a = fabsf(v.x); if (a > d0) { ms.x += a; cn.x += 1.f; }
        a = fabsf(v.y); if (a > d1) { ms.y += a; cn.y += 1.f; }
    }
    ms = blockReduceSum2(ms, sred, tid);
    cn = blockReduceSum2(cn, sred, tid);
    float a0v = ms.x / cn.x;
    float a1v = ms.y / cn.y;

    // tern -> BN -> maxpool2 -> relu, pair-interleaved out
    float2* outp = g_h1p + n2 * 4608;
    for (int p = tid; p < 4608; p += 256) {
        int c = p / 144;
        int r = p - c * 144;
        int py = r / 12, px = r - py * 12;
        float sc = __ldg(bng + c) * BN_INV, sh = __ldg(bnb + c);
        const float2* base = s_conv2 + c * 576 + (py * 2) * 24 + px * 2;
        float m0 = -1e30f, m1 = -1e30f;
#pragma unroll
        for (int dy = 0; dy < 2; dy++)
#pragma unroll
            for (int dx = 0; dx < 2; dx++) {
                float2 v = base[dy * 24 + dx];
                float t0 = (v.x > d0) ? a0v : ((v.x < -d0) ? -a0v : 0.f);
                float t1 = (v.y > d1) ? a1v : ((v.y < -d1) ? -a1v : 0.f);
                m0 = fmaxf(m0, t0 * sc + sh);
                m1 = fmaxf(m1, t1 * sc + sh);
            }
        outp[p] = make_float2(fmaxf(m0, 0.f), fmaxf(m1, 0.f));
    }
}

// ---------------------------------------------------------------------------
// Kernel 2: conv2(32->64, 5x5, 12->8) + tern + BN + maxpool2 + relu
// 2 samples/CTA f32x2. Reads pair-interleaved g_h1p, writes g_h2p.
// ---------------------------------------------------------------------------
__global__ __launch_bounds__(256) void k_conv2(
    const float* __restrict__ w, const float* __restrict__ bconv,
    const float* __restrict__ bng, const float* __restrict__ bnb) {
    extern __shared__ float smraw[];
    float2* s_in2   = (float2*)smraw;                 // 32 * 12 * 13 = 4992 float2
    float2* s_conv2 = (float2*)(smraw + 4992 * 2);    // 4096 float2
    __shared__ float sred[16];

    const int n2 = blockIdx.x;
    const int tid = threadIdx.x;

    const float2* xin = g_h1p + n2 * 4608;
    for (int i = tid; i < 4608; i += 256) {
        int ic = i / 144;
        int r  = i - ic * 144;
        int rr = r / 12, c = r - rr * 12;
        s_in2[ic * 156 + rr * 13 + c] = xin[i];
    }
    __syncthreads();

    const int oc = tid >> 2;
    const int q  = tid & 3;
    const int y0 = q * 2;

    u64 acc0[8], acc1[8];
    {
        float b = bconv[oc];
        u64 bb = pack2(b, b);
#pragma unroll
        for (int i = 0; i < 8; i++) { acc0[i] = bb; acc1[i] = bb; }
    }

    for (int ic = 0; ic < 32; ic++) {
        const float* wb = w + (oc * 32 + ic) * 25;
        float wv[25];
#pragma unroll
        for (int i = 0; i < 25; i++) wv[i] = __ldg(wb + i);
        const float2* ib = s_in2 + ic * 156;
#pragma unroll
        for (int rr = 0; rr < 6; rr++) {
            u64 row[12];
            const u64* rp = (const u64*)(ib + (y0 + rr) * 13);
#pragma unroll
            for (int j = 0; j < 12; j++) row[j] = rp[j];
            if (rr < 5) {
#pragma unroll
                for (int kw = 0; kw < 5; kw++) {
                    float s = wv[rr * 5 + kw];
                    u64 wd = pack2(s, s);
#pragma unroll
                    for (int ox = 0; ox < 8; ox++)
                        acc0[ox] = ffma2(wd, row[ox + kw], acc0[ox]);
                }
            }
            if (rr >= 1) {
#pragma unroll
                for (int kw = 0; kw < 5; kw++) {
                    float s = wv[(rr - 1) * 5 + kw];
                    u64 wd = pack2(s, s);
#pragma unroll
                    for (int ox = 0; ox < 8; ox++)
                        acc1[ox] = ffma2(wd, row[ox + kw], acc1[ox]);
                }
            }
        }
    }

    float2 labs = make_float2(0.f, 0.f);
#pragma unroll
    for (int ox = 0; ox < 8; ox++) {
        float2 v0 = unpack2(acc0[ox]);
        float2 v1 = unpack2(acc1[ox]);
        s_conv2[oc * 64 + y0 * 8 + ox]       = v0;
        s_conv2[oc * 64 + (y0 + 1) * 8 + ox] = v1;
        labs.x += fabsf(v0.x) + fabsf(v1.x);
        labs.y += fabsf(v0.y) + fabsf(v1.y);
    }

    float2 tot = blockReduceSum2(labs, sred, tid);
    float d0 = 0.7f * tot.x / 4096.0f;
    float d1 = 0.7f * tot.y / 4096.0f;

    float2 ms = make_float2(0.f, 0.f), cn = make_float2(0.f, 0.f);
#pragma unroll
    for (int ox = 0; ox < 8; ox++) {
        float2 v0 = unpack2(acc0[ox]);
        float2 v1 = unpack2(acc1[ox]);
        float a;
        a = fabsf(v0.x); if (a > d0) { ms.x += a; cn.x += 1.f; }
        a = fabsf(v1.x); if (a > d0) { ms.x += a; cn.x += 1.f; }
        a = fabsf(v0.y); if (a > d1) { ms.y += a; cn.y += 1.f; }
        a = fabsf(v1.y); if (a > d1) { ms.y += a; cn.y += 1.f; }
    }
    ms = blockReduceSum2(ms, sred, tid);
    cn = blockReduceSum2(cn, sred, tid);
    float a0v = ms.x / cn.x;
    float a1v = ms.y / cn.y;

    float2* outp = g_h2p + n2 * 1024;
    for (int p = tid; p < 1024; p += 256) {
        int c = p >> 4;
        int r = p & 15;
        int py = r >> 2, px = r & 3;
        float sc = bng[c] * BN_INV, sh = bnb[c];
        const float2* base = s_conv2 + c * 64 + (py * 2) * 8 + px * 2;
        float m0 = -1e30f, m1 = -1e30f;
#pragma unroll
        for (int dy = 0; dy < 2; dy++)
#pragma unroll
            for (int dx = 0; dx < 2; dx++) {
                float2 v = base[dy * 8 + dx];
                float t0 = (v.x > d0) ? a0v : ((v.x < -d0) ? -a0v : 0.f);
                float t1 = (v.y > d1) ? a1v : ((v.y < -d1) ? -a1v : 0.f);
                m0 = fmaxf(m0, t0 * sc + sh);
                m1 = fmaxf(m1, t1 * sc + sh);
            }
        outp[p] = make_float2(fmaxf(m0, 0.f), fmaxf(m1, 0.f));
    }
}

// ---------------------------------------------------------------------------
// Kernel 3: fc1 + tern + relu + fc2 + tern -> out
// 16 samples (8 pairs)/CTA, f32x2 lanes, depth-1 register prefetch of weights.
// ---------------------------------------------------------------------------
#define SH 516

__global__ __launch_bounds__(256) void k_fc(
    const float* __restrict__ b1, const float* __restrict__ w2,
    const float* __restrict__ b2, float* __restrict__ out) {
    extern __shared__ float sm[];
    float2* s_x2 = (float2*)sm;              // 8192 float2
    float*  s_h  = sm + 16384;               // 16*SH
    float*  s_o  = s_h + 16 * SH;            // 160
    float*  s_ad = s_o + 160;                // 32

    const int tid = threadIdx.x;
    const int pr0 = blockIdx.x * 8;
    const int n0  = blockIdx.x * 16;

    for (int i = tid; i < 8192; i += 256) s_x2[i] = g_h2p[pr0 * 1024 + i];
    __syncthreads();

    const int oc0 = tid, oc1 = tid + 256;
    u64 a0[8], a1[8];
    {
        float bA = b1[oc0], bB = b1[oc1];
        u64 pA = pack2(bA, bA), pB = pack2(bB, bB);
#pragma unroll
        for (int p = 0; p < 8; p++) { a0[p] = pA; a1[p] = pB; }
    }

    // depth-1 software pipeline on weight LDGs
    float cA[4], cB[4];
#pragma unroll
    for (int j = 0; j < 4; j++) {
        cA[j] = __ldg(&g_w1t[j * 512 + oc0]);
        cB[j] = __ldg(&g_w1t[j * 512 + oc1]);
    }

#pragma unroll 1
    for (int kt = 0; kt < 1024; kt += 4) {
        float nA[4], nB[4];
        if (kt + 4 < 1024) {
#pragma unroll
            for (int j = 0; j < 4; j++) {
                nA[j] = __ldg(&g_w1t[(kt + 4 + j) * 512 + oc0]);
                nB[j] = __ldg(&g_w1t[(kt + 4 + j) * 512 + oc1]);
            }
        } else {
#pragma unroll
            for (int j = 0; j < 4; j++) { nA[j] = 0.f; nB[j] = 0.f; }
        }

        u64 WA0 = pack2(cA[0], cA[0]), WA1 = pack2(cA[1], cA[1]);
        u64 WA2 = pack2(cA[2], cA[2]), WA3 = pack2(cA[3], cA[3]);
        u64 WB0 = pack2(cB[0], cB[0]), WB1 = pack2(cB[1], cB[1]);
        u64 WB2 = pack2(cB[2], cB[2]), WB3 = pack2(cB[3], cB[3]);
#pragma unroll
        for (int p = 0; p < 8; p++) {
            const ulonglong2* xp = (const ulonglong2*)(s_x2 + p * 1024 + kt);
            ulonglong2 xa = xp[0];
            ulonglong2 xb = xp[1];
            a0[p] = ffma2(WA0, xa.x, a0[p]);
            a0[p] = ffma2(WA1, xa.y, a0[p]);
            a0[p] = ffma2(WA2, xb.x, a0[p]);
            a0[p] = ffma2(WA3, xb.y, a0[p]);
            a1[p] = ffma2(WB0, xa.x, a1[p]);
            a1[p] = ffma2(WB1, xa.y, a1[p]);
            a1[p] = ffma2(WB2, xb.x, a1[p]);
            a1[p] = ffma2(WB3, xb.y, a1[p]);
        }
#pragma unroll
        for (int j = 0; j < 4; j++) { cA[j] = nA[j]; cB[j] = nB[j]; }
    }
    __syncthreads();

#pragma unroll
    for (int p = 0; p < 8; p++) {
        float2 v0 = unpack2(a0[p]);
        float2 v1 = unpack2(a1[p]);
        s_h[(2 * p) * SH + oc0]     = v0.x;
        s_h[(2 * p + 1) * SH + oc0] = v0.y;
        s_h[(2 * p) * SH + oc1]     = v1.x;
        s_h[(2 * p + 1) * SH + oc1] = v1.y;
    }
    __syncthreads();

    // per-sample ternarize params (16 groups of 16 lanes)
    {
        int s = tid >> 4, j = tid & 15;
        float sum = 0.f;
        for (int i = j; i < 512; i += 16) sum += fabsf(s_h[s * SH + i]);
#pragma unroll
        for (int o = 8; o > 0; o >>= 1) sum += __shfl_xor_sync(0xffffffffu, sum, o);
        float d = 0.7f * sum / 512.0f;
        float msv = 0.f, c = 0.f;
        for (int i = j; i < 512; i += 16) {
            float a = fabsf(s_h[s * SH + i]);
            if (a > d) { msv += a; c += 1.f; }
        }
#pragma unroll
        for (int o = 8; o > 0; o >>= 1) {
            msv += __shfl_xor_sync(0xffffffffu, msv, o);
            c   += __shfl_xor_sync(0xffffffffu, c, o);
        }
        if (j == 0) { s_ad[s] = d; s_ad[16 + s] = msv / c; }
    }
    __syncthreads();

    for (int i = tid; i < 8192; i += 256) {
        int s = i >> 9, k = i & 511;
        float v = s_h[s * SH + k];
        float d = s_ad[s], a = s_ad[16 + s];
        float t = (v > d) ? a : ((v < -d) ? -a : 0.f);
        s_h[s * SH + k] = fmaxf(t, 0.f);
    }
    __syncthreads();

    if (tid < 160) {
        int s = tid / 10, oc = tid - s * 10;
        float acc = b2[oc];
        const float* hp = s_h + s * SH;
        const float* wp = w2 + oc * 512;
#pragma unroll 4
        for (int k = 0; k < 512; k += 4) {
            float4 wv4 = *(const float4*)(wp + k);
            float4 hv4 = *(const float4*)(hp + k);
            acc += hv4.x * wv4.x + hv4.y * wv4.y + hv4.z * wv4.z + hv4.w * wv4.w;
        }
        s_o[s * 10 + oc] = acc;
    }
    __syncthreads();

    if (tid < 16) {
        int s = tid;
        float v[10];
        float sum = 0.f;
#pragma unroll
        for (int j = 0; j < 10; j++) {
            v[j] = s_o[s * 10 + j];
            sum += fabsf(v[j]);
        }
        float d = 0.7f * sum / 10.0f;
        float msv = 0.f, c = 0.f;
#pragma unroll
        for (int j = 0; j < 10; j++) {
            float a = fabsf(v[j]);
            if (a > d) { msv += a; c += 1.f; }
        }
        float a = msv / c;
        float* op = out + (n0 + s) * 10;
#pragma unroll
        for (int j = 0; j < 10; j++)
            op[j] = (v[j] > d) ? a : ((v[j] < -d) ? -a : 0.f);
    }
}

// ---------------------------------------------------------------------------
extern "C" void kernel_launch(void* const* d_in, const int* in_sizes, int n_in,
                              void* d_out, int out_size) {
    const float* x   = (const float*)d_in[0];
    const float* c1w = (const float*)d_in[1];
    const float* c1b = (const float*)d_in[2];
    const float* g1  = (const float*)d_in[3];
    const float* b1n = (const float*)d_in[4];
    const float* c2w = (const float*)d_in[5];
    const float* c2b = (const float*)d_in[6];
    const float* g2  = (const float*)d_in[7];
    const float* b2n = (const float*)d_in[8];
    const float* w1  = (const float*)d_in[9];
    const float* fb1 = (const float*)d_in[10];
    const float* w2  = (const float*)d_in[11];
    const float* fb2 = (const float*)d_in[12];
    float* out = (float*)d_out;

    const int B = in_sizes[0] / 784;

    const int smem1 = (2456 + 18432 * 2) * 4;     // 157,280 B
    const int smem2 = (4992 + 4096) * 8;          //  72,704 B
    const int smem3 = (16384 + 16 * SH + 192) * 4; // 99,328 B
    cudaFuncSetAttribute(k_conv1, cudaFuncAttributeMaxDynamicSharedMemorySize, smem1);
    cudaFuncSetAttribute(k_conv2, cudaFuncAttributeMaxDynamicSharedMemorySize, smem2);
    cudaFuncSetAttribute(k_fc,    cudaFuncAttributeMaxDynamicSharedMemorySize, smem3);

    k_tw1<<<dim3(32, 16), 256>>>(w1);
    k_conv1<<<B / 2, 256, smem1>>>(x, c1w, c1b, g1, b1n);
    k_conv2<<<B / 2, 256, smem2>>>(c2w, c2b, g2, b2n);
    k_fc<<<B / 16, 256, smem3>>>(fb1, w2, fb2, out);
}

// round 4
// speedup vs baseline: 1.2195x; 1.2195x over previous
#include <cuda_runtime.h>
#include <math.h>

#define BN_INV 0.9999950000374997f

typedef unsigned long long u64;

__device__ __forceinline__ u64 ffma2(u64 a, u64 b, u64 c) {
    u64 d;
    asm("fma.rn.f32x2 %0, %1, %2, %3;" : "=l"(d) : "l"(a), "l"(b), "l"(c));
    return d;
}
__device__ __forceinline__ u64 pack2(float lo, float hi) {
    u64 r;
    asm("mov.b64 %0, {%1, %2};" : "=l"(r) : "f"(lo), "f"(hi));
    return r;
}
__device__ __forceinline__ float2 unpack2(u64 v) {
    float2 f;
    asm("mov.b64 {%0, %1}, %2;" : "=f"(f.x), "=f"(f.y) : "l"(v));
    return f;
}

// Scratch (allocation-free rule -> __device__ globals)
__device__ float2 g_h1p[1024 * 4608];   // stage1 out, pair-interleaved
__device__ float2 g_h2p[1024 * 1024];   // stage2 out, pair-interleaved
__device__ float  g_w1t[1024 * 512];    // fc1 weights transposed [k][oc]

// ---------------------------------------------------------------------------
// Paired block reduce (256 threads = 8 warps); sred must hold >= 16 floats
// ---------------------------------------------------------------------------
__device__ __forceinline__ float2 blockReduceSum2(float2 v, volatile float* sred, int tid) {
#pragma unroll
    for (int o = 16; o > 0; o >>= 1) {
        v.x += __shfl_xor_sync(0xffffffffu, v.x, o);
        v.y += __shfl_xor_sync(0xffffffffu, v.y, o);
    }
    if ((tid & 31) == 0) {
        sred[(tid >> 5) * 2]     = v.x;
        sred[(tid >> 5) * 2 + 1] = v.y;
    }
    __syncthreads();
    if (tid < 32) {
        float a = (tid < 8) ? sred[tid * 2] : 0.f;
        float b = (tid < 8) ? sred[tid * 2 + 1] : 0.f;
#pragma unroll
        for (int o = 4; o > 0; o >>= 1) {
            a += __shfl_xor_sync(0xffffffffu, a, o);
            b += __shfl_xor_sync(0xffffffffu, b, o);
        }
        if (tid == 0) { sred[0] = a; sred[1] = b; }
    }
    __syncthreads();
    float2 r = make_float2(sred[0], sred[1]);
    __syncthreads();
    return r;
}

// ---------------------------------------------------------------------------
// Kernel 0: transpose fc1 weights  w1[512][1024] -> g_w1t[1024][512]
// ---------------------------------------------------------------------------
__global__ __launch_bounds__(256) void k_tw1(const float* __restrict__ w1) {
    __shared__ float t[32][33];
    int kb = blockIdx.x * 32;
    int ob = blockIdx.y * 32;
    int lx = threadIdx.x & 31, ly = threadIdx.x >> 5;
#pragma unroll
    for (int r = ly; r < 32; r += 8) t[r][lx] = w1[(ob + r) * 1024 + kb + lx];
    __syncthreads();
#pragma unroll
    for (int r = ly; r < 32; r += 8) g_w1t[(kb + r) * 512 + ob + lx] = t[lx][r];
}

// ---------------------------------------------------------------------------
// Kernel 1: conv1(1->32, 5x5, 28->24) + tern + BN + maxpool2 + relu
// 2 samples/CTA, f32x2. (unchanged)
// ---------------------------------------------------------------------------
__global__ __launch_bounds__(256) void k_conv1(
    const float* __restrict__ x, const float* __restrict__ w,
    const float* __restrict__ bconv, const float* __restrict__ bng,
    const float* __restrict__ bnb) {
    extern __shared__ float sm[];
    float2* s_in2   = (float2*)sm;            // 812 float2
    float*  s_w     = sm + 1624;              // 800
    float*  s_b     = sm + 2424;              // 32
    float2* s_conv2 = (float2*)(sm + 2456);   // 18432 float2
    __shared__ float sred[16];

    const int n2 = blockIdx.x;
    const int tid = threadIdx.x;

    const float* x0 = x + (2 * n2) * 784;
    const float* x1 = x + (2 * n2 + 1) * 784;
    for (int i = tid; i < 784; i += 256) {
        int r = i / 28, c = i - r * 28;
        s_in2[r * 29 + c] = make_float2(x0[i], x1[i]);
    }
    for (int i = tid; i < 800; i += 256) s_w[i] = w[i];
    if (tid < 32) s_b[tid] = bconv[tid];
    __syncthreads();

    float2 labs = make_float2(0.f, 0.f);
#pragma unroll
    for (int p = 0; p < 3; p++) {
        int pair = tid + p * 256;
        int oc = pair / 24, oy = pair - oc * 24;
        u64 acc[24];
        {
            float b = s_b[oc];
            u64 bb = pack2(b, b);
#pragma unroll
            for (int ox = 0; ox < 24; ox++) acc[ox] = bb;
        }
#pragma unroll
        for (int kh = 0; kh < 5; kh++) {
            u64 row[28];
            const u64* rp = (const u64*)(s_in2 + (oy + kh) * 29);
#pragma unroll
            for (int j = 0; j < 28; j++) row[j] = rp[j];
            const float* wp = s_w + oc * 25 + kh * 5;
#pragma unroll
            for (int kw = 0; kw < 5; kw++) {
                float s = wp[kw];
                u64 wd = pack2(s, s);
#pragma unroll
                for (int ox = 0; ox < 24; ox++)
                    acc[ox] = ffma2(wd, row[ox + kw], acc[ox]);
            }
        }
        float2* cp = s_conv2 + oc * 576 + oy * 24;
#pragma unroll
        for (int ox = 0; ox < 24; ox++) {
            float2 v = unpack2(acc[ox]);
            cp[ox] = v;
            labs.x += fabsf(v.x);
            labs.y += fabsf(v.y);
        }
    }

    float2 tot = blockReduceSum2(labs, sred, tid);
    float d0 = 0.7f * tot.x / 18432.0f;
    float d1 = 0.7f * tot.y / 18432.0f;

    float2 ms = make_float2(0.f, 0.f), cn = make_float2(0.f, 0.f);
    for (int i = tid; i < 18432; i += 256) {
        float2 v = s_conv2[i];
        float a;
        a = fabsf(v.x); if (a > d0) { ms.x += a; cn.x += 1.f; }
        a = fabsf(v.y); if (a > d1) { ms.y += a; cn.y += 1.f; }
    }
    ms = blockReduceSum2(ms, sred, tid);
    cn = blockReduceSum2(cn, sred, tid);
    float a0v = ms.x / cn.x;
    float a1v = ms.y / cn.y;

    float2* outp = g_h1p + n2 * 4608;
    for (int p = tid; p < 4608; p += 256) {
        int c = p / 144;
        int r = p - c * 144;
        int py = r / 12, px = r - py * 12;
        float sc = __ldg(bng + c) * BN_INV, sh = __ldg(bnb + c);
        const float2* base = s_conv2 + c * 576 + (py * 2) * 24 + px * 2;
        float m0 = -1e30f, m1 = -1e30f;
#pragma unroll
        for (int dy = 0; dy < 2; dy++)
#pragma unroll
            for (int dx = 0; dx < 2; dx++) {
                float2 v = base[dy * 24 + dx];
                float t0 = (v.x > d0) ? a0v : ((v.x < -d0) ? -a0v : 0.f);
                float t1 = (v.y > d1) ? a1v : ((v.y < -d1) ? -a1v : 0.f);
                m0 = fmaxf(m0, t0 * sc + sh);
                m1 = fmaxf(m1, t1 * sc + sh);
            }
        outp[p] = make_float2(fmaxf(m0, 0.f), fmaxf(m1, 0.f));
    }
}

// ---------------------------------------------------------------------------
// Kernel 2: conv2(32->64, 5x5, 12->8) + tern + BN + maxpool2 + relu
// 2 samples/CTA f32x2. Weights staged through smem in 4-ic chunks:
// coalesced LDG -> conflict-free broadcast LDS (kills the l1tex wavefront storm).
// ---------------------------------------------------------------------------
__global__ __launch_bounds__(256) void k_conv2(
    const float* __restrict__ w, const float* __restrict__ bconv,
    const float* __restrict__ bng, const float* __restrict__ bnb) {
    extern __shared__ float smraw[];
    float2* s_in2   = (float2*)smraw;                 // 4992 float2
    float2* s_conv2 = (float2*)(smraw + 4992 * 2);    // 4096 float2
    float*  s_wc    = smraw + (4992 + 4096) * 2;      // 6400 floats [oc][icl][25]
    __shared__ float sred[16];

    const int n2 = blockIdx.x;
    const int tid = threadIdx.x;

    const float2* xin = g_h1p + n2 * 4608;
    for (int i = tid; i < 4608; i += 256) {
        int ic = i / 144;
        int r  = i - ic * 144;
        int rr = r / 12, c = r - rr * 12;
        s_in2[ic * 156 + rr * 13 + c] = xin[i];
    }

    const int oc = tid >> 2;
    const int q  = tid & 3;
    const int y0 = q * 2;

    u64 acc0[8], acc1[8];
    {
        float b = __ldg(bconv + oc);
        u64 bb = pack2(b, b);
#pragma unroll
        for (int i = 0; i < 8; i++) { acc0[i] = bb; acc1[i] = bb; }
    }

    for (int icb = 0; icb < 32; icb += 4) {
        __syncthreads();
        // stage w[oc][icb..icb+3][25] -> s_wc[oc*100 + r], source runs of 100
        // consecutive floats per oc -> coalesced.
        for (int j = tid; j < 6400; j += 256) {
            int o = j / 100, r = j - o * 100;
            s_wc[j] = w[(o * 32 + icb) * 25 + r];
        }
        __syncthreads();

        const float* wbase = s_wc + oc * 100;
#pragma unroll
        for (int icl = 0; icl < 4; icl++) {
            float wv[25];
#pragma unroll
            for (int i = 0; i < 25; i++) wv[i] = wbase[icl * 25 + i];
            const float2* ib = s_in2 + (icb + icl) * 156;
#pragma unroll
            for (int rr = 0; rr < 6; rr++) {
                u64 row[12];
                const u64* rp = (const u64*)(ib + (y0 + rr) * 13);
#pragma unroll
                for (int j = 0; j < 12; j++) row[j] = rp[j];
                if (rr < 5) {
#pragma unroll
                    for (int kw = 0; kw < 5; kw++) {
                        float s = wv[rr * 5 + kw];
                        u64 wd = pack2(s, s);
#pragma unroll
                        for (int ox = 0; ox < 8; ox++)
                            acc0[ox] = ffma2(wd, row[ox + kw], acc0[ox]);
                    }
                }
                if (rr >= 1) {
#pragma unroll
                    for (int kw = 0; kw < 5; kw++) {
                        float s = wv[(rr - 1) * 5 + kw];
                        u64 wd = pack2(s, s);
#pragma unroll
                        for (int ox = 0; ox < 8; ox++)
                            acc1[ox] = ffma2(wd, row[ox + kw], acc1[ox]);
                    }
                }
            }
        }
    }
    __syncthreads();

    float2 labs = make_float2(0.f, 0.f);
#pragma unroll
    for (int ox = 0; ox < 8; ox++) {
        float2 v0 = unpack2(acc0[ox]);
        float2 v1 = unpack2(acc1[ox]);
        s_conv2[oc * 64 + y0 * 8 + ox]       = v0;
        s_conv2[oc * 64 + (y0 + 1) * 8 + ox] = v1;
        labs.x += fabsf(v0.x) + fabsf(v1.x);
        labs.y += fabsf(v0.y) + fabsf(v1.y);
    }

    float2 tot = blockReduceSum2(labs, sred, tid);
    float d0 = 0.7f * tot.x / 4096.0f;
    float d1 = 0.7f * tot.y / 4096.0f;

    float2 ms = make_float2(0.f, 0.f), cn = make_float2(0.f, 0.f);
#pragma unroll
    for (int ox = 0; ox < 8; ox++) {
        float2 v0 = unpack2(acc0[ox]);
        float2 v1 = unpack2(acc1[ox]);
        float a;
        a = fabsf(v0.x); if (a > d0) { ms.x += a; cn.x += 1.f; }
        a = fabsf(v1.x); if (a > d0) { ms.x += a; cn.x += 1.f; }
        a = fabsf(v0.y); if (a > d1) { ms.y += a; cn.y += 1.f; }
        a = fabsf(v1.y); if (a > d1) { ms.y += a; cn.y += 1.f; }
    }
    ms = blockReduceSum2(ms, sred, tid);
    cn = blockReduceSum2(cn, sred, tid);
    float a0v = ms.x / cn.x;
    float a1v = ms.y / cn.y;

    float2* outp = g_h2p + n2 * 1024;
    for (int p = tid; p < 1024; p += 256) {
        int c = p >> 4;
        int r = p & 15;
        int py = r >> 2, px = r & 3;
        float sc = __ldg(bng + c) * BN_INV, sh = __ldg(bnb + c);
        const float2* base = s_conv2 + c * 64 + (py * 2) * 8 + px * 2;
        float m0 = -1e30f, m1 = -1e30f;
#pragma unroll
        for (int dy = 0; dy < 2; dy++)
#pragma unroll
            for (int dx = 0; dx < 2; dx++) {
                float2 v = base[dy * 8 + dx];
                float t0 = (v.x > d0) ? a0v : ((v.x < -d0) ? -a0v : 0.f);
                float t1 = (v.y > d1) ? a1v : ((v.y < -d1) ? -a1v : 0.f);
                m0 = fmaxf(m0, t0 * sc + sh);
                m1 = fmaxf(m1, t1 * sc + sh);
            }
        outp[p] = make_float2(fmaxf(m0, 0.f), fmaxf(m1, 0.f));
    }
}

// ---------------------------------------------------------------------------
// Kernel 3: fc1 + tern + relu + fc2 + tern -> out
// 512 threads/CTA, 16 samples (8 pairs). Split-K: thread = (k-half, oc-pair),
// each thread: 2 oc x 512 k x 8 pairs. Partials summed through s_h.
// ---------------------------------------------------------------------------
#define SH 516

__global__ __launch_bounds__(512) void k_fc(
    const float* __restrict__ b1, const float* __restrict__ w2,
    const float* __restrict__ b2, float* __restrict__ out) {
    extern __shared__ float sm[];
    float2* s_x2 = (float2*)sm;              // 8192 float2
    float*  s_h  = sm + 16384;               // 16*SH
    float*  s_o  = s_h + 16 * SH;            // 160
    float*  s_ad = s_o + 160;                // 32

    const int tid = threadIdx.x;
    const int pr0 = blockIdx.x * 8;
    const int n0  = blockIdx.x * 16;

    for (int i = tid; i < 8192; i += 512) s_x2[i] = g_h2p[pr0 * 1024 + i];
    __syncthreads();

    const int half = tid >> 8;               // k-half: 0 or 1
    const int ocb  = tid & 255;
    const int oc0 = ocb, oc1 = ocb + 256;
    const int k0 = half * 512, kend = k0 + 512;

    u64 a0[8], a1[8];
    {
        u64 pA, pB;
        if (half == 0) {
            float bA = b1[oc0], bB = b1[oc1];
            pA = pack2(bA, bA); pB = pack2(bB, bB);
        } else {
            pA = 0; pB = 0;
        }
#pragma unroll
        for (int p = 0; p < 8; p++) { a0[p] = pA; a1[p] = pB; }
    }

    float cA[4], cB[4];
#pragma unroll
    for (int j = 0; j < 4; j++) {
        cA[j] = __ldg(&g_w1t[(k0 + j) * 512 + oc0]);
        cB[j] = __ldg(&g_w1t[(k0 + j) * 512 + oc1]);
    }

#pragma unroll 1
    for (int kt = k0; kt < kend; kt += 4) {
        float nA[4], nB[4];
        if (kt + 4 < kend) {
#pragma unroll
            for (int j = 0; j < 4; j++) {
                nA[j] = __ldg(&g_w1t[(kt + 4 + j) * 512 + oc0]);
                nB[j] = __ldg(&g_w1t[(kt + 4 + j) * 512 + oc1]);
            }
        } else {
#pragma unroll
            for (int j = 0; j < 4; j++) { nA[j] = 0.f; nB[j] = 0.f; }
        }

        u64 WA0 = pack2(cA[0], cA[0]), WA1 = pack2(cA[1], cA[1]);
        u64 WA2 = pack2(cA[2], cA[2]), WA3 = pack2(cA[3], cA[3]);
        u64 WB0 = pack2(cB[0], cB[0]), WB1 = pack2(cB[1], cB[1]);
        u64 WB2 = pack2(cB[2], cB[2]), WB3 = pack2(cB[3], cB[3]);
#pragma unroll
        for (int p = 0; p < 8; p++) {
            const ulonglong2* xp = (const ulonglong2*)(s_x2 + p * 1024 + kt);
            ulonglong2 xa = xp[0];
            ulonglong2 xb = xp[1];
            a0[p] = ffma2(WA0, xa.x, a0[p]);
            a0[p] = ffma2(WA1, xa.y, a0[p]);
            a0[p] = ffma2(WA2, xb.x, a0[p]);
            a0[p] = ffma2(WA3, xb.y, a0[p]);
            a1[p] = ffma2(WB0, xa.x, a1[p]);
            a1[p] = ffma2(WB1, xa.y, a1[p]);
            a1[p] = ffma2(WB2, xb.x, a1[p]);
            a1[p] = ffma2(WB3, xb.y, a1[p]);
        }
#pragma unroll
        for (int j = 0; j < 4; j++) { cA[j] = nA[j]; cB[j] = nB[j]; }
    }
    __syncthreads();

    // combine k-halves through s_h
    if (half == 0) {
#pragma unroll
        for (int p = 0; p < 8; p++) {
            float2 v0 = unpack2(a0[p]);
            float2 v1 = unpack2(a1[p]);
            s_h[(2 * p) * SH + oc0]     = v0.x;
            s_h[(2 * p + 1) * SH + oc0] = v0.y;
            s_h[(2 * p) * SH + oc1]     = v1.x;
            s_h[(2 * p + 1) * SH + oc1] = v1.y;
        }
    }
    __syncthreads();
    if (half == 1) {
#pragma unroll
        for (int p = 0; p < 8; p++) {
            float2 v0 = unpack2(a0[p]);
            float2 v1 = unpack2(a1[p]);
            s_h[(2 * p) * SH + oc0]     += v0.x;
            s_h[(2 * p + 1) * SH + oc0] += v0.y;
            s_h[(2 * p) * SH + oc1]     += v1.x;
            s_h[(2 * p + 1) * SH + oc1] += v1.y;
        }
    }
    __syncthreads();

    // per-sample ternarize params: warp s handles sample s (16 warps)
    {
        int s = tid >> 5, j = tid & 31;
        float sum = 0.f;
        for (int i = j; i < 512; i += 32) sum += fabsf(s_h[s * SH + i]);
#pragma unroll
        for (int o = 16; o > 0; o >>= 1) sum += __shfl_xor_sync(0xffffffffu, sum, o);
        float d = 0.7f * sum / 512.0f;
        float msv = 0.f, c = 0.f;
        for (int i = j; i < 512; i += 32) {
            float a = fabsf(s_h[s * SH + i]);
            if (a > d) { msv += a; c += 1.f; }
        }
#pragma unroll
        for (int o = 16; o > 0; o >>= 1) {
            msv += __shfl_xor_sync(0xffffffffu, msv, o);
            c   += __shfl_xor_sync(0xffffffffu, c, o);
        }
        if (j == 0) { s_ad[s] = d; s_ad[16 + s] = msv / c; }
    }
    __syncthreads();

    for (int i = tid; i < 8192; i += 512) {
        int s = i >> 9, k = i & 511;
        float v = s_h[s * SH + k];
        float d = s_ad[s], a = s_ad[16 + s];
        float t = (v > d) ? a : ((v < -d) ? -a : 0.f);
        s_h[s * SH + k] = fmaxf(t, 0.f);
    }
    __syncthreads();

    if (tid < 160) {
        int s = tid / 10, oc = tid - s * 10;
        float acc = b2[oc];
        const float* hp = s_h + s * SH;
        const float* wp = w2 + oc * 512;
#pragma unroll 4
        for (int k = 0; k < 512; k += 4) {
            float4 wv4 = *(const float4*)(wp + k);
            float4 hv4 = *(const float4*)(hp + k);
            acc += hv4.x * wv4.x + hv4.y * wv4.y + hv4.z * wv4.z + hv4.w * wv4.w;
        }
        s_o[s * 10 + oc] = acc;
    }
    __syncthreads();

    if (tid < 16) {
        int s = tid;
        float v[10];
        float sum = 0.f;
#pragma unroll
        for (int j = 0; j < 10; j++) {
            v[j] = s_o[s * 10 + j];
            sum += fabsf(v[j]);
        }
        float d = 0.7f * sum / 10.0f;
        float msv = 0.f, c = 0.f;
#pragma unroll
        for (int j = 0; j < 10; j++) {
            float a = fabsf(v[j]);
            if (a > d) { msv += a; c += 1.f; }
        }
        float a = msv / c;
        float* op = out + (n0 + s) * 10;
#pragma unroll
        for (int j = 0; j < 10; j++)
            op[j] = (v[j] > d) ? a : ((v[j] < -d) ? -a : 0.f);
    }
}

// ---------------------------------------------------------------------------
extern "C" void kernel_launch(void* const* d_in, const int* in_sizes, int n_in,
                              void* d_out, int out_size) {
    const float* x   = (const float*)d_in[0];
    const float* c1w = (const float*)d_in[1];
    const float* c1b = (const float*)d_in[2];
    const float* g1  = (const float*)d_in[3];
    const float* b1n = (const float*)d_in[4];
    const float* c2w = (const float*)d_in[5];
    const float* c2b = (const float*)d_in[6];
    const float* g2  = (const float*)d_in[7];
    const float* b2n = (const float*)d_in[8];
    const float* w1  = (const float*)d_in[9];
    const float* fb1 = (const float*)d_in[10];
    const float* w2  = (const float*)d_in[11];
    const float* fb2 = (const float*)d_in[12];
    float* out = (float*)d_out;

    const int B = in_sizes[0] / 784;

    const int smem1 = (2456 + 18432 * 2) * 4;        // 157,280 B
    const int smem2 = ((4992 + 4096) * 2 + 6400) * 4; //  98,304 B
    const int smem3 = (16384 + 16 * SH + 192) * 4;    //  99,328 B
    cudaFuncSetAttribute(k_conv1, cudaFuncAttributeMaxDynamicSharedMemorySize, smem1);
    cudaFuncSetAttribute(k_conv2, cudaFuncAttributeMaxDynamicSharedMemorySize, smem2);
    cudaFuncSetAttribute(k_fc,    cudaFuncAttributeMaxDynamicSharedMemorySize, smem3);

    k_tw1<<<dim3(32, 16), 256>>>(w1);
    k_conv1<<<B / 2, 256, smem1>>>(x, c1w, c1b, g1, b1n);
    k_conv2<<<B / 2, 256, smem2>>>(c2w, c2b, g2, b2n);
    k_fc<<<B / 16, 512, smem3>>>(fb1, w2, fb2, out);
}